// round 4
// baseline (speedup 1.0000x reference)
#include <cuda_runtime.h>
#include <cstdint>

// Problem constants (fixed by the reference):
//   NUM_BLOCKS=8192, BLOCK_SIZE=16, NUM_HEADS=8, HEAD_SIZE=128
//   NUM_TOKENS=65536, NUM_SLOTS = 8192*16 = 131072
//   per-slot payload = 8*128 fp32 = 1024 floats = 4096 bytes = 256 float4
#define NUM_SLOTS       131072
#define NUM_TOKENS      65536
#define VEC4_PER_SLOT   256
#define SLOTS_PER_BLOCK 8

// Scratch: inverse slot map. inv_map[slot] = token index writing that slot, or -1.
__device__ int g_inv_map[NUM_SLOTS];

__global__ void scatter_inv_map_kernel(const int* __restrict__ slot_mapping) {
    int i = blockIdx.x * blockDim.x + threadIdx.x;
    if (i < NUM_TOKENS) g_inv_map[slot_mapping[i]] = i;
}

// One block per 8 consecutive slots; 256 threads each move float4 #t of each
// of the 8 slots. 8 independent 16B loads front-batched per thread (MLP=8,
// 128 B in flight), fully coalesced. Streaming hints: zero reuse.
__global__ void __launch_bounds__(256) merge_write_kernel(
    const float4* __restrict__ to_cache,
    const float4* __restrict__ kv_cache,
    float4* __restrict__ out)
{
    const unsigned slot_base = blockIdx.x * SLOTS_PER_BLOCK;
    const unsigned t = threadIdx.x;

    // Per-slot source resolution (8 ints, two 16B cachelines, broadcast).
    const float4* srcp[SLOTS_PER_BLOCK];
#pragma unroll
    for (int s = 0; s < SLOTS_PER_BLOCK; s++) {
        const unsigned slot = slot_base + s;
        const int src = g_inv_map[slot];
        srcp[s] = (src >= 0) ? (to_cache + (size_t)src * VEC4_PER_SLOT)
                             : (kv_cache + (size_t)slot * VEC4_PER_SLOT);
    }

    // Front-batch 8 independent loads, then 8 stores.
    float4 v[SLOTS_PER_BLOCK];
#pragma unroll
    for (int s = 0; s < SLOTS_PER_BLOCK; s++)
        v[s] = __ldcs(srcp[s] + t);

    float4* __restrict__ dst = out + (size_t)slot_base * VEC4_PER_SLOT + t;
#pragma unroll
    for (int s = 0; s < SLOTS_PER_BLOCK; s++)
        __stcs(dst + (size_t)s * VEC4_PER_SLOT, v[s]);
}

extern "C" void kernel_launch(void* const* d_in, const int* in_sizes, int n_in,
                              void* d_out, int out_size)
{
    const float4* to_cache     = (const float4*)d_in[0];  // [65536, 8, 128] f32
    const float4* kv_cache     = (const float4*)d_in[1];  // [8192, 16, 8, 128] f32
    const int*    slot_mapping = (const int*)d_in[2];     // [65536] i32
    float4*       out          = (float4*)d_out;          // full updated kv_cache

    // Init inv_map to -1 via memset node (0xFF bytes == -1 int).
    void* inv_map_ptr = nullptr;
    cudaGetSymbolAddress(&inv_map_ptr, g_inv_map);
    cudaMemsetAsync(inv_map_ptr, 0xFF, NUM_SLOTS * sizeof(int));

    scatter_inv_map_kernel<<<(NUM_TOKENS + 255) / 256, 256>>>(slot_mapping);
    merge_write_kernel<<<NUM_SLOTS / SLOTS_PER_BLOCK, 256>>>(to_cache, kv_cache, out);
}

// round 5
// speedup vs baseline: 1.0230x; 1.0230x over previous
#include <cuda_runtime.h>
#include <cstdint>

// Problem constants (fixed by the reference):
//   NUM_BLOCKS=8192, BLOCK_SIZE=16, NUM_HEADS=8, HEAD_SIZE=128
//   NUM_TOKENS=65536, NUM_SLOTS = 8192*16 = 131072
//   per-slot payload = 8*128 fp32 = 1024 floats = 4096 bytes = 256 float4
#define NUM_SLOTS       131072
#define NUM_TOKENS      65536
#define VEC4_PER_SLOT   256
#define SLOTS_PER_BLOCK 4

// Scratch: inverse slot map. inv_map[slot] = token index writing that slot, or -1.
__device__ int g_inv_map[NUM_SLOTS];

__global__ void scatter_inv_map_kernel(const int* __restrict__ slot_mapping) {
    int i = blockIdx.x * blockDim.x + threadIdx.x;
    if (i < NUM_TOKENS) g_inv_map[slot_mapping[i]] = i;
}

// One block per 4 consecutive slots; 256 threads each move float4 #t of each
// of the 4 slots. 4 independent 16B loads front-batched per thread (MLP=4),
// fully coalesced, low register pressure (occ ~84%). Streaming hints: zero reuse.
__global__ void __launch_bounds__(256, 8) merge_write_kernel(
    const float4* __restrict__ to_cache,
    const float4* __restrict__ kv_cache,
    float4* __restrict__ out)
{
    const unsigned slot_base = blockIdx.x * SLOTS_PER_BLOCK;
    const unsigned t = threadIdx.x;

    // Per-slot source resolution (4 ints, one 16B cacheline, broadcast).
    const float4* srcp[SLOTS_PER_BLOCK];
#pragma unroll
    for (int s = 0; s < SLOTS_PER_BLOCK; s++) {
        const unsigned slot = slot_base + s;
        const int src = g_inv_map[slot];
        srcp[s] = (src >= 0) ? (to_cache + (size_t)src * VEC4_PER_SLOT)
                             : (kv_cache + (size_t)slot * VEC4_PER_SLOT);
    }

    // Front-batch the 4 independent loads, then the 4 stores.
    float4 v[SLOTS_PER_BLOCK];
#pragma unroll
    for (int s = 0; s < SLOTS_PER_BLOCK; s++)
        v[s] = __ldcs(srcp[s] + t);

    float4* __restrict__ dst = out + (size_t)slot_base * VEC4_PER_SLOT + t;
#pragma unroll
    for (int s = 0; s < SLOTS_PER_BLOCK; s++)
        __stcs(dst + (size_t)s * VEC4_PER_SLOT, v[s]);
}

extern "C" void kernel_launch(void* const* d_in, const int* in_sizes, int n_in,
                              void* d_out, int out_size)
{
    const float4* to_cache     = (const float4*)d_in[0];  // [65536, 8, 128] f32
    const float4* kv_cache     = (const float4*)d_in[1];  // [8192, 16, 8, 128] f32
    const int*    slot_mapping = (const int*)d_in[2];     // [65536] i32
    float4*       out          = (float4*)d_out;          // full updated kv_cache

    // Init inv_map to -1 via memset node (0xFF bytes == -1 int).
    void* inv_map_ptr = nullptr;
    cudaGetSymbolAddress(&inv_map_ptr, g_inv_map);
    cudaMemsetAsync(inv_map_ptr, 0xFF, NUM_SLOTS * sizeof(int));

    scatter_inv_map_kernel<<<NUM_TOKENS / 512, 512>>>(slot_mapping);
    merge_write_kernel<<<NUM_SLOTS / SLOTS_PER_BLOCK, 256>>>(to_cache, kv_cache, out);
}

// round 6
// speedup vs baseline: 1.0292x; 1.0061x over previous
#include <cuda_runtime.h>
#include <cstdint>

// Problem constants (fixed by the reference):
//   NUM_BLOCKS=8192, BLOCK_SIZE=16, NUM_HEADS=8, HEAD_SIZE=128
//   NUM_TOKENS=65536, NUM_SLOTS = 8192*16 = 131072
//   per-slot payload = 8*128 fp32 = 1024 floats = 4096 bytes = 256 float4
#define NUM_SLOTS       131072
#define NUM_TOKENS      65536
#define VEC4_PER_SLOT   256
#define SLOTS_PER_BLOCK 4

// Inverse slot map, encoded token+1 (0 = slot untouched).
// INVARIANT: all-zero at entry to kernel_launch. Zero-initialized at module
// load; the merge kernel restores every entry it consumes back to zero, so
// every call sees the same initial state and does identical work.
__device__ int g_inv_map[NUM_SLOTS];

__global__ void scatter_inv_map_kernel(const int* __restrict__ slot_mapping) {
    int i = blockIdx.x * blockDim.x + threadIdx.x;
    if (i < NUM_TOKENS) g_inv_map[slot_mapping[i]] = i + 1;
}

// One block per 4 consecutive slots; 256 threads each move float4 #t of each
// of the 4 slots. 4 independent 16B loads front-batched per thread (MLP=4),
// fully coalesced, low register pressure (occ ~84%). Streaming hints: zero
// reuse. After reading its 4 map entries (single int4), the block restores
// them to zero (thread 0, behind a barrier) to maintain the invariant.
__global__ void __launch_bounds__(256, 8) merge_write_kernel(
    const float4* __restrict__ to_cache,
    const float4* __restrict__ kv_cache,
    float4* __restrict__ out)
{
    const unsigned slot_base = blockIdx.x * SLOTS_PER_BLOCK;
    const unsigned t = threadIdx.x;

    // All 4 map entries in one 16B broadcast load.
    const int4 m = *(const int4*)&g_inv_map[slot_base];
    const int srcs[SLOTS_PER_BLOCK] = { m.x, m.y, m.z, m.w };

    const float4* srcp[SLOTS_PER_BLOCK];
#pragma unroll
    for (int s = 0; s < SLOTS_PER_BLOCK; s++) {
        const unsigned slot = slot_base + s;
        srcp[s] = (srcs[s] > 0) ? (to_cache + (size_t)(srcs[s] - 1) * VEC4_PER_SLOT)
                                : (kv_cache + (size_t)slot * VEC4_PER_SLOT);
    }

    // Front-batch the 4 independent payload loads (in flight across the barrier).
    float4 v[SLOTS_PER_BLOCK];
#pragma unroll
    for (int s = 0; s < SLOTS_PER_BLOCK; s++)
        v[s] = __ldcs(srcp[s] + t);

    // All warps have read the map entries; now it is safe to clear them.
    __syncthreads();
    if (t == 0)
        *(int4*)&g_inv_map[slot_base] = make_int4(0, 0, 0, 0);

#pragma unroll
    for (int s = 0; s < SLOTS_PER_BLOCK; s++)
        __stcs(out + (size_t)(slot_base + s) * VEC4_PER_SLOT + t, v[s]);
}

extern "C" void kernel_launch(void* const* d_in, const int* in_sizes, int n_in,
                              void* d_out, int out_size)
{
    const float4* to_cache     = (const float4*)d_in[0];  // [65536, 8, 128] f32
    const float4* kv_cache     = (const float4*)d_in[1];  // [8192, 16, 8, 128] f32
    const int*    slot_mapping = (const int*)d_in[2];     // [65536] i32
    float4*       out          = (float4*)d_out;          // full updated kv_cache

    scatter_inv_map_kernel<<<NUM_TOKENS / 512, 512>>>(slot_mapping);
    merge_write_kernel<<<NUM_SLOTS / SLOTS_PER_BLOCK, 256>>>(to_cache, kv_cache, out);
}